// round 1
// baseline (speedup 1.0000x reference)
#include <cuda_runtime.h>
#include <math.h>

#define TPB   256
#define QCAP  2048
#define JN    128
#define SPLITS 8

// ---------------------------------------------------------------------------
// zero the output (d_out is poisoned by the harness)
// ---------------------------------------------------------------------------
__global__ void rf_zero_kernel(float* __restrict__ out, int n) {
    int i = blockIdx.x * blockDim.x + threadIdx.x;
    if (i < n) out[i] = 0.0f;
}

// ---------------------------------------------------------------------------
// process the compacted queue of active points for this block's patch.
// All lanes read the same sC[j] -> broadcast LDS, conflict-free.
// tanh(x) = 1 - 2/(exp(2x)+1): MUFU.EX2 + MUFU.RCP, accurate to ~1e-6,
// and safe at extremes (e->inf gives 1, e->0 gives -1, no inf/inf NaN).
// ---------------------------------------------------------------------------
__device__ __forceinline__ void rf_process_queue(
    const float4* __restrict__ sC, const int* __restrict__ sQ, int cnt,
    const float2* __restrict__ p2, float c0, float c1,
    float* __restrict__ out)
{
    for (int i = threadIdx.x; i < cnt; i += TPB) {
        const int n = sQ[i];
        const float2 pv = p2[n];
        const float s0 = (pv.x - c0) * 4.0f;
        const float s1 = (pv.y - c1) * 4.0f;
        float acc0 = 0.0f, acc1 = 0.0f;
        #pragma unroll 8
        for (int j = 0; j < JN; j += 2) {
            const float4 ca = sC[j];
            const float4 cb = sC[j + 1];
            float a0 = fmaf(s0, ca.x, fmaf(s1, ca.y, ca.z));
            float a1 = fmaf(s0, cb.x, fmaf(s1, cb.y, cb.z));
            float e0 = __expf(2.0f * a0);
            float e1 = __expf(2.0f * a1);
            float t0 = 1.0f - __fdividef(2.0f, e0 + 1.0f);
            float t1 = 1.0f - __fdividef(2.0f, e1 + 1.0f);
            acc0 = fmaf(t0, ca.w, acc0);
            acc1 = fmaf(t1, cb.w, acc1);
        }
        atomicAdd(&out[n], acc0 + acc1);
    }
}

// ---------------------------------------------------------------------------
// main kernel: blockIdx.x = patch m, blockIdx.y = point split.
// Phase 1: stream points of the split, compact active indices into smem queue.
// Phase 2: dense processing of the queue.
// ---------------------------------------------------------------------------
__global__ void __launch_bounds__(TPB)
rf_kernel(const float* __restrict__ p,  const float* __restrict__ cs,
          const float* __restrict__ W,  const float* __restrict__ b,
          const float* __restrict__ um, float* __restrict__ out,
          int N, int nPer)
{
    __shared__ float4 sC[JN];
    __shared__ int    sQ[QCAP];
    __shared__ int    sCnt;

    const int m   = blockIdx.x;
    const int tid = threadIdx.x;

    // patch constants -> smem (W is [Mp, 2, Jn])
    for (int j = tid; j < JN; j += TPB) {
        sC[j] = make_float4(W[m * (2 * JN) + j],
                            W[m * (2 * JN) + JN + j],
                            b[m * JN + j],
                            um[m * JN + j]);
    }
    const float c0 = cs[2 * m];
    const float c1 = cs[2 * m + 1];
    if (tid == 0) sCnt = 0;
    __syncthreads();

    const int n0 = blockIdx.y * nPer;
    const int n1 = min(n0 + nPer, N);
    const float2* p2 = (const float2*)p;

    for (int base = n0; base < n1; base += TPB) {
        const int n = base + tid;
        if (n < n1) {
            const float2 pv = p2[n];
            if (fabsf(pv.x - c0) <= 0.25f && fabsf(pv.y - c1) <= 0.25f) {
                const int pos = atomicAdd(&sCnt, 1);
                sQ[pos] = n;
            }
        }
        __syncthreads();                       // pushes of this stride visible
        if (sCnt > QCAP - TPB) {               // safety drain (never in practice)
            rf_process_queue(sC, sQ, sCnt, p2, c0, c1, out);
            __syncthreads();
            if (tid == 0) sCnt = 0;
            __syncthreads();
        }
    }
    // final drain (loop ended with a __syncthreads, sCnt is consistent)
    rf_process_queue(sC, sQ, sCnt, p2, c0, c1, out);
}

// ---------------------------------------------------------------------------
// inputs (metadata order): p[N,2] f32, cs[128,2] f32, W[128,2,128] f32,
//                          b[128,128] f32, um[128,128] f32 ; out [N,1] f32
// ---------------------------------------------------------------------------
extern "C" void kernel_launch(void* const* d_in, const int* in_sizes, int n_in,
                              void* d_out, int out_size)
{
    const float* p  = (const float*)d_in[0];
    const float* cs = (const float*)d_in[1];
    const float* W  = (const float*)d_in[2];
    const float* b  = (const float*)d_in[3];
    const float* um = (const float*)d_in[4];
    float* out = (float*)d_out;

    const int N  = in_sizes[0] / 2;   // 32768
    const int Mp = in_sizes[1] / 2;   // 128

    rf_zero_kernel<<<(out_size + TPB - 1) / TPB, TPB>>>(out, out_size);

    const int nPer = (N + SPLITS - 1) / SPLITS;
    dim3 grid(Mp, SPLITS);
    rf_kernel<<<grid, TPB>>>(p, cs, W, b, um, out, N, nPer);
}